// round 14
// baseline (speedup 1.0000x reference)
#include <cuda_runtime.h>
#include <cuda_fp16.h>
#include <cstdint>
#include <cstddef>

typedef unsigned int u32;

#define Bq 4
#define Sq 2048
#define Dm 1024
#define Hh 16
#define DP 64
#define MTOK (Bq*Sq)          /* 8192 */
#define NBH  (Bq*Hh)          /* 64   */
#define OUT_ELEMS (MTOK*Dm)   /* 8388608 */
#define NMW (Sq/32)           /* 64 mask words per row */

// Scratch (allocation-free rule: __device__ globals)
__device__ __half g_q16[(size_t)NBH*Sq*DP];
__device__ __half g_k16[(size_t)NBH*Sq*DP];
__device__ __half g_v16[(size_t)NBH*Sq*DP];
__device__ __half g_rep16[(size_t)MTOK*Dm];
__device__ __half g_e16[(size_t)NBH*Sq*Sq];      // unnormalized exp scores
__device__ u32    g_mbits[(size_t)Bq*Sq*NMW];
__device__ float  g_attn_fallback[(size_t)NBH*Sq*Sq];

// fp16 copies of inputs & weights
__device__ __half g_xq[(size_t)MTOK*Dm];
__device__ __half g_xk[(size_t)MTOK*Dm];
__device__ __half g_xv[(size_t)MTOK*Dm];
__device__ __half g_wq[(size_t)Dm*Dm];
__device__ __half g_wk[(size_t)Dm*Dm];
__device__ __half g_wv[(size_t)Dm*Dm];
__device__ __half g_wo[(size_t)Dm*Dm];

// ---------------------------------------------------------------------------
// helpers
// ---------------------------------------------------------------------------
__device__ __forceinline__ u32 saddr(const void* p) {
    return (u32)__cvta_generic_to_shared(p);
}
__device__ __forceinline__ u32 hpair(float a, float b) {
    __half2 t = __floats2half2_rn(a, b);
    return *reinterpret_cast<u32*>(&t);
}
__device__ __forceinline__ void mma16816(float* c, const u32* a, const u32* b) {
    asm volatile(
        "mma.sync.aligned.m16n8k16.row.col.f32.f16.f16.f32 "
        "{%0,%1,%2,%3},{%4,%5,%6,%7},{%8,%9},{%0,%1,%2,%3};"
        : "+f"(c[0]), "+f"(c[1]), "+f"(c[2]), "+f"(c[3])
        : "r"(a[0]), "r"(a[1]), "r"(a[2]), "r"(a[3]), "r"(b[0]), "r"(b[1]));
}
__device__ __forceinline__ void ldsm4(u32* r, u32 a) {
    asm volatile("ldmatrix.sync.aligned.m8n8.x4.shared.b16 {%0,%1,%2,%3},[%4];"
                 : "=r"(r[0]), "=r"(r[1]), "=r"(r[2]), "=r"(r[3]) : "r"(a));
}
__device__ __forceinline__ void ldsm4t(u32* r, u32 a) {
    asm volatile("ldmatrix.sync.aligned.m8n8.x4.trans.shared.b16 {%0,%1,%2,%3},[%4];"
                 : "=r"(r[0]), "=r"(r[1]), "=r"(r[2]), "=r"(r[3]) : "r"(a));
}
__device__ __forceinline__ void cpa16(u32 dst, const void* src) {
    asm volatile("cp.async.ca.shared.global [%0],[%1],16;\n" :: "r"(dst), "l"(src));
}
__device__ __forceinline__ void cpa_commit() {
    asm volatile("cp.async.commit_group;\n");
}
__device__ __forceinline__ void cpa_wait0() {
    asm volatile("cp.async.wait_group 0;\n");
}

#define PAW 36   /* 64-fp16 row: 32 words + 4 pad (144B pitch) */
#define PBW 68   /* 128-fp16 row: 64 words + 4 pad (272B pitch) */

// ---------------------------------------------------------------------------
// fp32 -> fp16 converts: QKV (3 tensors) in one launch; weights (4) in one.
// ---------------------------------------------------------------------------
__global__ __launch_bounds__(256) void cvt3_kernel(
    const float* __restrict__ A, const float* __restrict__ B,
    const float* __restrict__ C, __half* __restrict__ oa,
    __half* __restrict__ ob, __half* __restrict__ oc, int n8)
{
    const float* in = (blockIdx.y == 0) ? A : (blockIdx.y == 1) ? B : C;
    __half* out = (blockIdx.y == 0) ? oa : (blockIdx.y == 1) ? ob : oc;
    int i = blockIdx.x * 256 + threadIdx.x;
    int stride = gridDim.x * 256;
    for (; i < n8; i += stride) {
        float4 a = *(const float4*)&in[(size_t)i * 8];
        float4 b = *(const float4*)&in[(size_t)i * 8 + 4];
        uint4 w;
        w.x = hpair(a.x, a.y); w.y = hpair(a.z, a.w);
        w.z = hpair(b.x, b.y); w.w = hpair(b.z, b.w);
        *(uint4*)&out[(size_t)i * 8] = w;
    }
}

__global__ __launch_bounds__(256) void cvtw_kernel(
    const float* __restrict__ A, const float* __restrict__ B,
    const float* __restrict__ C, const float* __restrict__ D,
    __half* __restrict__ oa, __half* __restrict__ ob,
    __half* __restrict__ oc, __half* __restrict__ od, int n8)
{
    const float* in = (blockIdx.y == 0) ? A : (blockIdx.y == 1) ? B
                     : (blockIdx.y == 2) ? C : D;
    __half* out = (blockIdx.y == 0) ? oa : (blockIdx.y == 1) ? ob
                 : (blockIdx.y == 2) ? oc : od;
    int i = blockIdx.x * 256 + threadIdx.x;
    int stride = gridDim.x * 256;
    for (; i < n8; i += stride) {
        float4 a = *(const float4*)&in[(size_t)i * 8];
        float4 b = *(const float4*)&in[(size_t)i * 8 + 4];
        uint4 w;
        w.x = hpair(a.x, a.y); w.y = hpair(a.z, a.w);
        w.z = hpair(b.x, b.y); w.w = hpair(b.z, b.w);
        *(uint4*)&out[(size_t)i * 8] = w;
    }
}

// ---------------------------------------------------------------------------
// Mask -> bitmask. 1 bit per mask element (1 = masked). Warp ballot pack.
// ---------------------------------------------------------------------------
__global__ __launch_bounds__(256) void mask_bits_kernel(const float* __restrict__ M)
{
    int wgl = blockIdx.x * 8 + (threadIdx.x >> 5);
    int lane = threadIdx.x & 31;
#pragma unroll
    for (int i = 0; i < 8; i++) {
        size_t word = (size_t)wgl * 8 + i;
        float v = M[word * 32 + lane];
        u32 bal = __ballot_sync(0xffffffffu, v != 0.0f);
        if (lane == 0) { g_mbits[word] = bal; }
    }
}

// ---------------------------------------------------------------------------
// Projection GEMM, pure fp16 + cp.async double buffer (R11-proven).
// Y = X16 @ W16 + b, M=8192 N=1024 K=1024.
// targets 0/1/2 -> fp16 head-split out; 3 -> fp32 row-major dout.
// ---------------------------------------------------------------------------
#define PJ_XS0 0
#define PJ_XS1 18432
#define PJ_WS0 36864
#define PJ_WS1 54272
#define PJ_TOT 71680

__global__ __launch_bounds__(256) void proj_mma(
    const __half* __restrict__ X16, const __half* __restrict__ W16,
    const float* __restrict__ bias, float* __restrict__ dout, int target)
{
    extern __shared__ __align__(16) char sm[];

    const int tid = threadIdx.x;
    const int m0 = blockIdx.x * 128, n0 = blockIdx.y * 128;
    const int warp = tid >> 5, lane = tid & 31;
    const int wm = (warp >> 2) * 64, wn = (warp & 3) * 32;
    const int g = lane >> 2, tig = lane & 3;

    const int a_row = (lane & 7) + ((lane >> 3) & 1) * 8;
    const int a_k   = (lane >> 4) * 8;
    const int bt_k  = (lane & 7) + ((lane >> 3) & 1) * 8;
    const int bt_n  = (lane >> 4) * 8;

    const u32 smb = saddr(sm);

    float acc[4][4][4];
#pragma unroll
    for (int i = 0; i < 4; i++) {
#pragma unroll
        for (int j = 0; j < 4; j++) {
#pragma unroll
            for (int r = 0; r < 4; r++) { acc[i][j][r] = 0.0f; }
        }
    }

    {
        u32 xd = smb + PJ_XS0, wd = smb + PJ_WS0;
#pragma unroll
        for (int l = 0; l < 4; l++) {
            int idx = tid + l * 256;
            int r = idx >> 3, c = idx & 7;
            cpa16(xd + (u32)(r * PAW + c * 4) * 4u, X16 + (size_t)(m0 + r) * Dm + c * 8);
        }
#pragma unroll
        for (int l = 0; l < 4; l++) {
            int idx = tid + l * 256;
            int r = idx >> 4, c = idx & 15;
            cpa16(wd + (u32)(r * PBW + c * 4) * 4u, W16 + (size_t)r * Dm + n0 + c * 8);
        }
        cpa_commit();
    }

    int buf = 0;
    for (int it = 0; it < 16; it++) {
        cpa_wait0();
        __syncthreads();

        if (it < 15) {
            int kk0 = (it + 1) * 64;
            int nb = buf ^ 1;
            u32 xd = smb + (nb ? PJ_XS1 : PJ_XS0);
            u32 wd = smb + (nb ? PJ_WS1 : PJ_WS0);
#pragma unroll
            for (int l = 0; l < 4; l++) {
                int idx = tid + l * 256;
                int r = idx >> 3, c = idx & 7;
                cpa16(xd + (u32)(r * PAW + c * 4) * 4u, X16 + (size_t)(m0 + r) * Dm + kk0 + c * 8);
            }
#pragma unroll
            for (int l = 0; l < 4; l++) {
                int idx = tid + l * 256;
                int r = idx >> 4, c = idx & 15;
                cpa16(wd + (u32)(r * PBW + c * 4) * 4u, W16 + (size_t)(kk0 + r) * Dm + n0 + c * 8);
            }
            cpa_commit();
        }

        const u32 as_base = smb + (buf ? PJ_XS1 : PJ_XS0);
        const u32 bs_base = smb + (buf ? PJ_WS1 : PJ_WS0);

#pragma unroll
        for (int ks = 0; ks < 64; ks += 16) {
            u32 af[4][4];
#pragma unroll
            for (int mi = 0; mi < 4; mi++) {
                ldsm4(af[mi], as_base + (u32)((wm + mi * 16 + a_row) * PAW + ((ks + a_k) >> 1)) * 4u);
            }
            u32 bf[2][4];
#pragma unroll
            for (int h = 0; h < 2; h++) {
                ldsm4t(bf[h], bs_base + (u32)((ks + bt_k) * PBW + ((wn + h * 16 + bt_n) >> 1)) * 4u);
            }
#pragma unroll
            for (int mi = 0; mi < 4; mi++) {
#pragma unroll
                for (int j = 0; j < 4; j++) {
                    mma16816(acc[mi][j], af[mi], &bf[j >> 1][(j & 1) * 2]);
                }
            }
        }
        __syncthreads();
        buf ^= 1;
    }

    __half* hs_out = (target == 0) ? g_q16 : (target == 1) ? g_k16 : g_v16;
#pragma unroll
    for (int mi = 0; mi < 4; mi++) {
        int row = m0 + wm + mi * 16 + g;
        int row2 = row + 8;
#pragma unroll
        for (int j = 0; j < 4; j++) {
            int col = n0 + wn + j * 8 + tig * 2;
            float b0 = bias[col], b1 = bias[col + 1];
            float c00 = acc[mi][j][0] + b0, c01 = acc[mi][j][1] + b1;
            float c10 = acc[mi][j][2] + b0, c11 = acc[mi][j][3] + b1;
            if (target < 3) {
                int h = col >> 6, dc = col & 63;
                int bi = row >> 11, sl = row & 2047;
                int bi2 = row2 >> 11, sl2 = row2 & 2047;
                *(u32*)&hs_out[((size_t)(bi * Hh + h) * Sq + sl) * DP + dc] = hpair(c00, c01);
                *(u32*)&hs_out[((size_t)(bi2 * Hh + h) * Sq + sl2) * DP + dc] = hpair(c10, c11);
            } else {
                *(float2*)&dout[(size_t)row * Dm + col] = make_float2(c00, c01);
                *(float2*)&dout[(size_t)row2 * Dm + col] = make_float2(c10, c11);
            }
        }
    }
}

// ---------------------------------------------------------------------------
// Fused flash attention + in-kernel normalize epilogue.
// Block owns 128 q-rows of one (b,h). Per K/V tile: QK mma -> exp -> store e16
// -> rowsum regs -> P repack -> O+=PV. After loop: inv to smem, then stream
// this block's own e16 rows (L2-hot) -> normalized fp32 attn.
// ---------------------------------------------------------------------------
#define SM_QS   0
#define SM_KS   18432
#define SM_VS   55296
#define SM_MS   92160
#define SM_INV  96256
#define SM_TOT  96768

__global__ __launch_bounds__(256) void flash_mma(float* __restrict__ attn)
{
    extern __shared__ __align__(16) char sm[];
    const int tid = threadIdx.x;
    const int bh = blockIdx.y, b = bh >> 4, h = bh & 15;
    const int m0 = blockIdx.x * 128;
    const __half* Qp = g_q16 + (size_t)bh * Sq * DP;
    const __half* Kp = g_k16 + (size_t)bh * Sq * DP;
    const __half* Vp = g_v16 + (size_t)bh * Sq * DP;
    const int warp = tid >> 5, lane = tid & 31;
    const int wm = warp * 16;
    const int g = lane >> 2, tig = lane & 3;

    const int a_row = (lane & 7) + ((lane >> 3) & 1) * 8;
    const int a_k   = (lane >> 4) * 8;
    const int bn_n  = (lane & 7) + (lane >> 4) * 8;
    const int bn_k  = ((lane >> 3) & 1) * 8;
    const int bt_k  = (lane & 7) + ((lane >> 3) & 1) * 8;
    const int bt_n  = (lane >> 4) * 8;

    const u32 smb = saddr(sm);
    u32* Qs = (u32*)(sm + SM_QS);

#pragma unroll
    for (int l = 0; l < 4; l++) {
        int idx = tid + l * 256;
        int r = idx >> 3, q = idx & 7;
        *(uint4*)&Qs[r * PAW + q * 4] = *(const uint4*)&Qp[(size_t)(m0 + r) * DP + q * 8];
    }

    {
        u32 ksb = smb + SM_KS, vsb = smb + SM_VS, msb = smb + SM_MS;
#pragma unroll
        for (int l = 0; l < 4; l++) {
            int idx = tid + l * 256;
            int r = idx >> 3, c = idx & 7;
            cpa16(ksb + (u32)(r * PAW + c * 4) * 4u, Kp + (size_t)r * DP + c * 8);
            cpa16(vsb + (u32)(r * PAW + c * 4) * 4u, Vp + (size_t)r * DP + c * 8);
        }
        if (tid < 128) {
            cpa16(msb + tid * 16, g_mbits + (size_t)(b * Sq + m0 + tid) * NMW);
        }
        cpa_commit();
    }
    __syncthreads();

    u32 af[4][4];
#pragma unroll
    for (int ks = 0; ks < 4; ks++) {
        ldsm4(af[ks], smb + SM_QS + (u32)((wm + a_row) * PAW + ((ks * 16 + a_k) >> 1)) * 4u);
    }

    float o[8][4];
#pragma unroll
    for (int t = 0; t < 8; t++) {
#pragma unroll
        for (int r = 0; r < 4; r++) { o[t][r] = 0.0f; }
    }
    float rs0 = 0.0f, rs1 = 0.0f;

    const float scale = 0.125f;
    __half* er0 = g_e16 + ((size_t)bh * Sq + m0 + wm + g) * Sq;
    __half* er1 = g_e16 + ((size_t)bh * Sq + m0 + wm + g + 8) * Sq;

    int buf = 0;
    for (int it = 0; it < 16; it++) {
        int n0 = it * 128;
        cpa_wait0();
        __syncthreads();

        if (it < 15) {
            int nn = n0 + 128;
            int nb = buf ^ 1;
            u32 ksb = smb + SM_KS + nb * 18432;
            u32 vsb = smb + SM_VS + nb * 18432;
            u32 msb = smb + SM_MS + nb * 2048;
#pragma unroll
            for (int l = 0; l < 4; l++) {
                int idx = tid + l * 256;
                int r = idx >> 3, c = idx & 7;
                cpa16(ksb + (u32)(r * PAW + c * 4) * 4u, Kp + (size_t)(nn + r) * DP + c * 8);
                cpa16(vsb + (u32)(r * PAW + c * 4) * 4u, Vp + (size_t)(nn + r) * DP + c * 8);
            }
            if (tid < 128) {
                cpa16(msb + tid * 16, g_mbits + (size_t)(b * Sq + m0 + tid) * NMW + (nn >> 5));
            }
            cpa_commit();
        }

        const u32 ks_base = smb + SM_KS + buf * 18432;
        const u32 vs_base = smb + SM_VS + buf * 18432;
        const uint4* Ms = (const uint4*)(sm + SM_MS + buf * 2048);

        float sc[16][4];
#pragma unroll
        for (int t = 0; t < 16; t++) {
#pragma unroll
            for (int r = 0; r < 4; r++) { sc[t][r] = 0.0f; }
        }
#pragma unroll
        for (int ks = 0; ks < 4; ks++) {
#pragma unroll
            for (int h6 = 0; h6 < 8; h6++) {
                u32 bq[4];
                ldsm4(bq, ks_base + (u32)((h6 * 16 + bn_n) * PAW + ((ks * 16 + bn_k) >> 1)) * 4u);
                mma16816(sc[2 * h6], af[ks], &bq[0]);
                mma16816(sc[2 * h6 + 1], af[ks], &bq[2]);
            }
        }

        uint4 mq0 = Ms[wm + g];
        uint4 mq1 = Ms[wm + g + 8];
        const u32* mw0 = (const u32*)&mq0;
        const u32* mw1 = (const u32*)&mq1;
        u32 pa[8][4];
#pragma unroll
        for (int t = 0; t < 16; t++) {
            int bp = t * 8 + tig * 2;
            u32 b0 = (mw0[bp >> 5] >> (bp & 31)) & 3u;
            u32 b1 = (mw1[bp >> 5] >> (bp & 31)) & 3u;
            float e0 = (b0 & 1u) ? 0.0f : __expf(sc[t][0] * scale);
            float e1 = (b0 & 2u) ? 0.0f : __expf(sc[t][1] * scale);
            float e2 = (b1 & 1u) ? 0.0f : __expf(sc[t][2] * scale);
            float e3 = (b1 & 2u) ? 0.0f : __expf(sc[t][3] * scale);
            rs0 += e0 + e1;
            rs1 += e2 + e3;
            int col = n0 + t * 8 + tig * 2;
            u32 w01 = hpair(e0, e1);
            u32 w23 = hpair(e2, e3);
            *(u32*)&er0[col] = w01;
            *(u32*)&er1[col] = w23;
            pa[t >> 1][(t & 1) * 2]     = w01;
            pa[t >> 1][(t & 1) * 2 + 1] = w23;
        }

#pragma unroll
        for (int kk = 0; kk < 8; kk++) {
#pragma unroll
            for (int hh = 0; hh < 4; hh++) {
                u32 bv[4];
                ldsm4t(bv, vs_base + (u32)((kk * 16 + bt_k) * PAW + ((hh * 16 + bt_n) >> 1)) * 4u);
                mma16816(o[2 * hh], pa[kk], &bv[0]);
                mma16816(o[2 * hh + 1], pa[kk], &bv[2]);
            }
        }
        buf ^= 1;
    }

    rs0 += __shfl_xor_sync(0xffffffffu, rs0, 1);
    rs0 += __shfl_xor_sync(0xffffffffu, rs0, 2);
    rs1 += __shfl_xor_sync(0xffffffffu, rs1, 1);
    rs1 += __shfl_xor_sync(0xffffffffu, rs1, 2);
    float iv0 = 1.0f / rs0;
    float iv1 = 1.0f / rs1;
    float* invs = (float*)(sm + SM_INV);
    if (tig == 0) {
        invs[wm + g] = iv0;
        invs[wm + g + 8] = iv1;
    }

    int row = m0 + wm + g;
    int row2 = row + 8;
#pragma unroll
    for (int t = 0; t < 8; t++) {
        int col = t * 8 + tig * 2;
        *(u32*)&g_rep16[(size_t)(b * Sq + row) * Dm + h * DP + col] =
            hpair(o[t][0] * iv0, o[t][1] * iv0);
        *(u32*)&g_rep16[(size_t)(b * Sq + row2) * Dm + h * DP + col] =
            hpair(o[t][2] * iv1, o[t][3] * iv1);
    }

    // ---- in-kernel normalize: this block's 128 rows, e16 (L2-hot) -> attn ----
    __syncthreads();
    const __half* eb = g_e16 + ((size_t)bh * Sq + m0) * Sq;
    float* ab = attn + ((size_t)bh * Sq + m0) * Sq;
#pragma unroll 4
    for (int i = 0; i < 128; i++) {
        int idx = tid + i * 256;          // 128 rows x 256 chunks of 8 halves
        int r = idx >> 8, c = idx & 255;
        float iv = invs[r];
        uint4 w = *(const uint4*)&eb[(size_t)r * Sq + c * 8];
        const __half2* hp = (const __half2*)&w;
        float2 p0 = __half22float2(hp[0]);
        float2 p1 = __half22float2(hp[1]);
        float2 p2 = __half22float2(hp[2]);
        float2 p3 = __half22float2(hp[3]);
        float* dst = &ab[(size_t)r * Sq + c * 8];
        *(float4*)dst = make_float4(p0.x * iv, p0.y * iv, p1.x * iv, p1.y * iv);
        *(float4*)(dst + 4) = make_float4(p2.x * iv, p2.y * iv, p3.x * iv, p3.y * iv);
    }
}

// ---------------------------------------------------------------------------
extern "C" void kernel_launch(void* const* d_in, const int* in_sizes, int n_in,
                              void* d_out, int out_size)
{
    const float* Q    = (const float*)d_in[0];
    const float* K    = (const float*)d_in[1];
    const float* V    = (const float*)d_in[2];
    const float* Mask = (const float*)d_in[3];
    const float* Wq   = (const float*)d_in[4];
    const float* bq   = (const float*)d_in[5];
    const float* Wk   = (const float*)d_in[6];
    const float* bk   = (const float*)d_in[7];
    const float* Wv   = (const float*)d_in[8];
    const float* bv   = (const float*)d_in[9];
    const float* Wo   = (const float*)d_in[10];
    const float* bo   = (const float*)d_in[11];

    float* out = (float*)d_out;

    float* attn;
    const size_t attn_elems = (size_t)NBH * Sq * Sq;
    if ((size_t)out_size >= (size_t)OUT_ELEMS + attn_elems) {
        attn = out + OUT_ELEMS;
    } else {
        void* p = nullptr;
        cudaGetSymbolAddress(&p, g_attn_fallback);
        attn = (float*)p;
    }

    static __half *xq, *xk, *xv, *wq, *wk, *wv, *wo, *rep;
    static bool init_done = false;
    if (!init_done) {
        cudaFuncSetAttribute(flash_mma, cudaFuncAttributeMaxDynamicSharedMemorySize, SM_TOT);
        cudaFuncSetAttribute(proj_mma, cudaFuncAttributeMaxDynamicSharedMemorySize, PJ_TOT);
        void* p;
        cudaGetSymbolAddress(&p, g_xq); xq = (__half*)p;
        cudaGetSymbolAddress(&p, g_xk); xk = (__half*)p;
        cudaGetSymbolAddress(&p, g_xv); xv = (__half*)p;
        cudaGetSymbolAddress(&p, g_wq); wq = (__half*)p;
        cudaGetSymbolAddress(&p, g_wk); wk = (__half*)p;
        cudaGetSymbolAddress(&p, g_wv); wv = (__half*)p;
        cudaGetSymbolAddress(&p, g_wo); wo = (__half*)p;
        cudaGetSymbolAddress(&p, g_rep16); rep = (__half*)p;
        init_done = true;
    }

    // converts (merged launches)
    cvt3_kernel<<<dim3(1024, 3), 256>>>(Q, K, V, xq, xk, xv, OUT_ELEMS / 8);
    cvtw_kernel<<<dim3(256, 4), 256>>>(Wq, Wk, Wv, Wo, wq, wk, wv, wo, (Dm * Dm) / 8);

    mask_bits_kernel<<<(Bq * Sq * NMW) / 64, 256>>>(Mask);

    dim3 gProj(MTOK / 128, Dm / 128);            // 64 x 8
    proj_mma<<<gProj, 256, PJ_TOT>>>(xq, wq, bq, nullptr, 0);
    proj_mma<<<gProj, 256, PJ_TOT>>>(xk, wk, bk, nullptr, 1);
    proj_mma<<<gProj, 256, PJ_TOT>>>(xv, wv, bv, nullptr, 2);

    dim3 gAttn(Sq / 128, NBH);                   // 16 x 64
    flash_mma<<<gAttn, 256, SM_TOT>>>(attn);

    proj_mma<<<gProj, 256, PJ_TOT>>>(rep, wo, bo, out, 3);
}

// round 15
// speedup vs baseline: 1.3427x; 1.3427x over previous
#include <cuda_runtime.h>
#include <cuda_fp16.h>
#include <cstdint>
#include <cstddef>

typedef unsigned int u32;

#define Bq 4
#define Sq 2048
#define Dm 1024
#define Hh 16
#define DP 64
#define MTOK (Bq*Sq)          /* 8192 */
#define NBH  (Bq*Hh)          /* 64   */
#define OUT_ELEMS (MTOK*Dm)   /* 8388608 */
#define NMW (Sq/32)           /* 64 mask words per row */

// Scratch (allocation-free rule: __device__ globals)
__device__ __half g_q16[(size_t)NBH*Sq*DP];
__device__ __half g_k16[(size_t)NBH*Sq*DP];
__device__ __half g_v16[(size_t)NBH*Sq*DP];
__device__ __half g_rep16[(size_t)MTOK*Dm];
__device__ __half g_e16[(size_t)NBH*Sq*Sq];      // unnormalized exp scores
__device__ float  g_inv[(size_t)NBH*Sq];          // 1 / rowsum
__device__ u32    g_mbits[(size_t)Bq*Sq*NMW];
__device__ float  g_attn_fallback[(size_t)NBH*Sq*Sq];

// fp16 copies of inputs & weights
__device__ __half g_xq[(size_t)MTOK*Dm];
__device__ __half g_xk[(size_t)MTOK*Dm];
__device__ __half g_xv[(size_t)MTOK*Dm];
__device__ __half g_wq[(size_t)Dm*Dm];
__device__ __half g_wk[(size_t)Dm*Dm];
__device__ __half g_wv[(size_t)Dm*Dm];
__device__ __half g_wo[(size_t)Dm*Dm];

// ---------------------------------------------------------------------------
// helpers
// ---------------------------------------------------------------------------
__device__ __forceinline__ u32 saddr(const void* p) {
    return (u32)__cvta_generic_to_shared(p);
}
__device__ __forceinline__ u32 hpair(float a, float b) {
    __half2 t = __floats2half2_rn(a, b);
    return *reinterpret_cast<u32*>(&t);
}
__device__ __forceinline__ void mma16816(float* c, const u32* a, const u32* b) {
    asm volatile(
        "mma.sync.aligned.m16n8k16.row.col.f32.f16.f16.f32 "
        "{%0,%1,%2,%3},{%4,%5,%6,%7},{%8,%9},{%0,%1,%2,%3};"
        : "+f"(c[0]), "+f"(c[1]), "+f"(c[2]), "+f"(c[3])
        : "r"(a[0]), "r"(a[1]), "r"(a[2]), "r"(a[3]), "r"(b[0]), "r"(b[1]));
}
__device__ __forceinline__ void ldsm4(u32* r, u32 a) {
    asm volatile("ldmatrix.sync.aligned.m8n8.x4.shared.b16 {%0,%1,%2,%3},[%4];"
                 : "=r"(r[0]), "=r"(r[1]), "=r"(r[2]), "=r"(r[3]) : "r"(a));
}
__device__ __forceinline__ void ldsm4t(u32* r, u32 a) {
    asm volatile("ldmatrix.sync.aligned.m8n8.x4.trans.shared.b16 {%0,%1,%2,%3},[%4];"
                 : "=r"(r[0]), "=r"(r[1]), "=r"(r[2]), "=r"(r[3]) : "r"(a));
}
__device__ __forceinline__ void cpa16(u32 dst, const void* src) {
    asm volatile("cp.async.ca.shared.global [%0],[%1],16;\n" :: "r"(dst), "l"(src));
}
__device__ __forceinline__ void cpa_commit() {
    asm volatile("cp.async.commit_group;\n");
}
__device__ __forceinline__ void cpa_wait0() {
    asm volatile("cp.async.wait_group 0;\n");
}

#define PAW 36   /* 64-fp16 row: 32 words + 4 pad (144B pitch) */
#define PBW 68   /* 128-fp16 row: 64 words + 4 pad (272B pitch) */

// ---------------------------------------------------------------------------
// fp32 -> fp16 converts: QKV (3 tensors) in one launch; weights (4) in one.
// ---------------------------------------------------------------------------
__global__ __launch_bounds__(256) void cvt3_kernel(
    const float* __restrict__ A, const float* __restrict__ B,
    const float* __restrict__ C, __half* __restrict__ oa,
    __half* __restrict__ ob, __half* __restrict__ oc, int n8)
{
    const float* in = (blockIdx.y == 0) ? A : (blockIdx.y == 1) ? B : C;
    __half* out = (blockIdx.y == 0) ? oa : (blockIdx.y == 1) ? ob : oc;
    int i = blockIdx.x * 256 + threadIdx.x;
    int stride = gridDim.x * 256;
    for (; i < n8; i += stride) {
        float4 a = *(const float4*)&in[(size_t)i * 8];
        float4 b = *(const float4*)&in[(size_t)i * 8 + 4];
        uint4 w;
        w.x = hpair(a.x, a.y); w.y = hpair(a.z, a.w);
        w.z = hpair(b.x, b.y); w.w = hpair(b.z, b.w);
        *(uint4*)&out[(size_t)i * 8] = w;
    }
}

__global__ __launch_bounds__(256) void cvtw_kernel(
    const float* __restrict__ A, const float* __restrict__ B,
    const float* __restrict__ C, const float* __restrict__ D,
    __half* __restrict__ oa, __half* __restrict__ ob,
    __half* __restrict__ oc, __half* __restrict__ od, int n8)
{
    const float* in = (blockIdx.y == 0) ? A : (blockIdx.y == 1) ? B
                     : (blockIdx.y == 2) ? C : D;
    __half* out = (blockIdx.y == 0) ? oa : (blockIdx.y == 1) ? ob
                 : (blockIdx.y == 2) ? oc : od;
    int i = blockIdx.x * 256 + threadIdx.x;
    int stride = gridDim.x * 256;
    for (; i < n8; i += stride) {
        float4 a = *(const float4*)&in[(size_t)i * 8];
        float4 b = *(const float4*)&in[(size_t)i * 8 + 4];
        uint4 w;
        w.x = hpair(a.x, a.y); w.y = hpair(a.z, a.w);
        w.z = hpair(b.x, b.y); w.w = hpair(b.z, b.w);
        *(uint4*)&out[(size_t)i * 8] = w;
    }
}

// ---------------------------------------------------------------------------
// Mask -> bitmask. 1 bit per mask element (1 = masked). Warp ballot pack.
// ---------------------------------------------------------------------------
__global__ __launch_bounds__(256) void mask_bits_kernel(const float* __restrict__ M)
{
    int wgl = blockIdx.x * 8 + (threadIdx.x >> 5);
    int lane = threadIdx.x & 31;
#pragma unroll
    for (int i = 0; i < 8; i++) {
        size_t word = (size_t)wgl * 8 + i;
        float v = M[word * 32 + lane];
        u32 bal = __ballot_sync(0xffffffffu, v != 0.0f);
        if (lane == 0) { g_mbits[word] = bal; }
    }
}

// ---------------------------------------------------------------------------
// Projection GEMM, pure fp16 + cp.async double buffer (R11-proven).
// Y = X16 @ W16 + b, M=8192 N=1024 K=1024.
// targets 0/1/2 -> fp16 head-split out; 3 -> fp32 row-major dout.
// ---------------------------------------------------------------------------
#define PJ_XS0 0
#define PJ_XS1 18432
#define PJ_WS0 36864
#define PJ_WS1 54272
#define PJ_TOT 71680

__global__ __launch_bounds__(256) void proj_mma(
    const __half* __restrict__ X16, const __half* __restrict__ W16,
    const float* __restrict__ bias, float* __restrict__ dout, int target)
{
    extern __shared__ __align__(16) char sm[];

    const int tid = threadIdx.x;
    const int m0 = blockIdx.x * 128, n0 = blockIdx.y * 128;
    const int warp = tid >> 5, lane = tid & 31;
    const int wm = (warp >> 2) * 64, wn = (warp & 3) * 32;
    const int g = lane >> 2, tig = lane & 3;

    const int a_row = (lane & 7) + ((lane >> 3) & 1) * 8;
    const int a_k   = (lane >> 4) * 8;
    const int bt_k  = (lane & 7) + ((lane >> 3) & 1) * 8;
    const int bt_n  = (lane >> 4) * 8;

    const u32 smb = saddr(sm);

    float acc[4][4][4];
#pragma unroll
    for (int i = 0; i < 4; i++) {
#pragma unroll
        for (int j = 0; j < 4; j++) {
#pragma unroll
            for (int r = 0; r < 4; r++) { acc[i][j][r] = 0.0f; }
        }
    }

    {
        u32 xd = smb + PJ_XS0, wd = smb + PJ_WS0;
#pragma unroll
        for (int l = 0; l < 4; l++) {
            int idx = tid + l * 256;
            int r = idx >> 3, c = idx & 7;
            cpa16(xd + (u32)(r * PAW + c * 4) * 4u, X16 + (size_t)(m0 + r) * Dm + c * 8);
        }
#pragma unroll
        for (int l = 0; l < 4; l++) {
            int idx = tid + l * 256;
            int r = idx >> 4, c = idx & 15;
            cpa16(wd + (u32)(r * PBW + c * 4) * 4u, W16 + (size_t)r * Dm + n0 + c * 8);
        }
        cpa_commit();
    }

    int buf = 0;
    for (int it = 0; it < 16; it++) {
        cpa_wait0();
        __syncthreads();

        if (it < 15) {
            int kk0 = (it + 1) * 64;
            int nb = buf ^ 1;
            u32 xd = smb + (nb ? PJ_XS1 : PJ_XS0);
            u32 wd = smb + (nb ? PJ_WS1 : PJ_WS0);
#pragma unroll
            for (int l = 0; l < 4; l++) {
                int idx = tid + l * 256;
                int r = idx >> 3, c = idx & 7;
                cpa16(xd + (u32)(r * PAW + c * 4) * 4u, X16 + (size_t)(m0 + r) * Dm + kk0 + c * 8);
            }
#pragma unroll
            for (int l = 0; l < 4; l++) {
                int idx = tid + l * 256;
                int r = idx >> 4, c = idx & 15;
                cpa16(wd + (u32)(r * PBW + c * 4) * 4u, W16 + (size_t)(kk0 + r) * Dm + n0 + c * 8);
            }
            cpa_commit();
        }

        const u32 as_base = smb + (buf ? PJ_XS1 : PJ_XS0);
        const u32 bs_base = smb + (buf ? PJ_WS1 : PJ_WS0);

#pragma unroll
        for (int ks = 0; ks < 64; ks += 16) {
            u32 af[4][4];
#pragma unroll
            for (int mi = 0; mi < 4; mi++) {
                ldsm4(af[mi], as_base + (u32)((wm + mi * 16 + a_row) * PAW + ((ks + a_k) >> 1)) * 4u);
            }
            u32 bf[2][4];
#pragma unroll
            for (int h = 0; h < 2; h++) {
                ldsm4t(bf[h], bs_base + (u32)((ks + bt_k) * PBW + ((wn + h * 16 + bt_n) >> 1)) * 4u);
            }
#pragma unroll
            for (int mi = 0; mi < 4; mi++) {
#pragma unroll
                for (int j = 0; j < 4; j++) {
                    mma16816(acc[mi][j], af[mi], &bf[j >> 1][(j & 1) * 2]);
                }
            }
        }
        __syncthreads();
        buf ^= 1;
    }

    __half* hs_out = (target == 0) ? g_q16 : (target == 1) ? g_k16 : g_v16;
#pragma unroll
    for (int mi = 0; mi < 4; mi++) {
        int row = m0 + wm + mi * 16 + g;
        int row2 = row + 8;
#pragma unroll
        for (int j = 0; j < 4; j++) {
            int col = n0 + wn + j * 8 + tig * 2;
            float b0 = bias[col], b1 = bias[col + 1];
            float c00 = acc[mi][j][0] + b0, c01 = acc[mi][j][1] + b1;
            float c10 = acc[mi][j][2] + b0, c11 = acc[mi][j][3] + b1;
            if (target < 3) {
                int h = col >> 6, dc = col & 63;
                int bi = row >> 11, sl = row & 2047;
                int bi2 = row2 >> 11, sl2 = row2 & 2047;
                *(u32*)&hs_out[((size_t)(bi * Hh + h) * Sq + sl) * DP + dc] = hpair(c00, c01);
                *(u32*)&hs_out[((size_t)(bi2 * Hh + h) * Sq + sl2) * DP + dc] = hpair(c10, c11);
            } else {
                *(float2*)&dout[(size_t)row * Dm + col] = make_float2(c00, c01);
                *(float2*)&dout[(size_t)row2 * Dm + col] = make_float2(c10, c11);
            }
        }
    }
}

// ---------------------------------------------------------------------------
// Fused flash attention pass (R11-proven, no epilogue).
// Block owns 128 q-rows of one (b,h). Per K/V tile: QK mma -> exp -> store e16
// -> rowsum regs -> P repack -> O+=PV. cp.async double-buffered tiles.
// End: g_inv = 1/rowsum; g_rep16 = O * inv.
// ---------------------------------------------------------------------------
#define SM_QS   0
#define SM_KS   18432
#define SM_VS   55296
#define SM_MS   92160
#define SM_TOT  96256

__global__ __launch_bounds__(256) void flash_mma()
{
    extern __shared__ __align__(16) char sm[];
    const int tid = threadIdx.x;
    const int bh = blockIdx.y, b = bh >> 4, h = bh & 15;
    const int m0 = blockIdx.x * 128;
    const __half* Qp = g_q16 + (size_t)bh * Sq * DP;
    const __half* Kp = g_k16 + (size_t)bh * Sq * DP;
    const __half* Vp = g_v16 + (size_t)bh * Sq * DP;
    const int warp = tid >> 5, lane = tid & 31;
    const int wm = warp * 16;
    const int g = lane >> 2, tig = lane & 3;

    const int a_row = (lane & 7) + ((lane >> 3) & 1) * 8;
    const int a_k   = (lane >> 4) * 8;
    const int bn_n  = (lane & 7) + (lane >> 4) * 8;
    const int bn_k  = ((lane >> 3) & 1) * 8;
    const int bt_k  = (lane & 7) + ((lane >> 3) & 1) * 8;
    const int bt_n  = (lane >> 4) * 8;

    const u32 smb = saddr(sm);
    u32* Qs = (u32*)(sm + SM_QS);

#pragma unroll
    for (int l = 0; l < 4; l++) {
        int idx = tid + l * 256;
        int r = idx >> 3, q = idx & 7;
        *(uint4*)&Qs[r * PAW + q * 4] = *(const uint4*)&Qp[(size_t)(m0 + r) * DP + q * 8];
    }

    {
        u32 ksb = smb + SM_KS, vsb = smb + SM_VS, msb = smb + SM_MS;
#pragma unroll
        for (int l = 0; l < 4; l++) {
            int idx = tid + l * 256;
            int r = idx >> 3, c = idx & 7;
            cpa16(ksb + (u32)(r * PAW + c * 4) * 4u, Kp + (size_t)r * DP + c * 8);
            cpa16(vsb + (u32)(r * PAW + c * 4) * 4u, Vp + (size_t)r * DP + c * 8);
        }
        if (tid < 128) {
            cpa16(msb + tid * 16, g_mbits + (size_t)(b * Sq + m0 + tid) * NMW);
        }
        cpa_commit();
    }
    __syncthreads();

    u32 af[4][4];
#pragma unroll
    for (int ks = 0; ks < 4; ks++) {
        ldsm4(af[ks], smb + SM_QS + (u32)((wm + a_row) * PAW + ((ks * 16 + a_k) >> 1)) * 4u);
    }

    float o[8][4];
#pragma unroll
    for (int t = 0; t < 8; t++) {
#pragma unroll
        for (int r = 0; r < 4; r++) { o[t][r] = 0.0f; }
    }
    float rs0 = 0.0f, rs1 = 0.0f;

    const float scale = 0.125f;
    __half* er0 = g_e16 + ((size_t)bh * Sq + m0 + wm + g) * Sq;
    __half* er1 = g_e16 + ((size_t)bh * Sq + m0 + wm + g + 8) * Sq;

    int buf = 0;
    for (int it = 0; it < 16; it++) {
        int n0 = it * 128;
        cpa_wait0();
        __syncthreads();

        if (it < 15) {
            int nn = n0 + 128;
            int nb = buf ^ 1;
            u32 ksb = smb + SM_KS + nb * 18432;
            u32 vsb = smb + SM_VS + nb * 18432;
            u32 msb = smb + SM_MS + nb * 2048;
#pragma unroll
            for (int l = 0; l < 4; l++) {
                int idx = tid + l * 256;
                int r = idx >> 3, c = idx & 7;
                cpa16(ksb + (u32)(r * PAW + c * 4) * 4u, Kp + (size_t)(nn + r) * DP + c * 8);
                cpa16(vsb + (u32)(r * PAW + c * 4) * 4u, Vp + (size_t)(nn + r) * DP + c * 8);
            }
            if (tid < 128) {
                cpa16(msb + tid * 16, g_mbits + (size_t)(b * Sq + m0 + tid) * NMW + (nn >> 5));
            }
            cpa_commit();
        }

        const u32 ks_base = smb + SM_KS + buf * 18432;
        const u32 vs_base = smb + SM_VS + buf * 18432;
        const uint4* Ms = (const uint4*)(sm + SM_MS + buf * 2048);

        float sc[16][4];
#pragma unroll
        for (int t = 0; t < 16; t++) {
#pragma unroll
            for (int r = 0; r < 4; r++) { sc[t][r] = 0.0f; }
        }
#pragma unroll
        for (int ks = 0; ks < 4; ks++) {
#pragma unroll
            for (int h6 = 0; h6 < 8; h6++) {
                u32 bq[4];
                ldsm4(bq, ks_base + (u32)((h6 * 16 + bn_n) * PAW + ((ks * 16 + bn_k) >> 1)) * 4u);
                mma16816(sc[2 * h6], af[ks], &bq[0]);
                mma16816(sc[2 * h6 + 1], af[ks], &bq[2]);
            }
        }

        uint4 mq0 = Ms[wm + g];
        uint4 mq1 = Ms[wm + g + 8];
        const u32* mw0 = (const u32*)&mq0;
        const u32* mw1 = (const u32*)&mq1;
        u32 pa[8][4];
#pragma unroll
        for (int t = 0; t < 16; t++) {
            int bp = t * 8 + tig * 2;
            u32 b0 = (mw0[bp >> 5] >> (bp & 31)) & 3u;
            u32 b1 = (mw1[bp >> 5] >> (bp & 31)) & 3u;
            float e0 = (b0 & 1u) ? 0.0f : __expf(sc[t][0] * scale);
            float e1 = (b0 & 2u) ? 0.0f : __expf(sc[t][1] * scale);
            float e2 = (b1 & 1u) ? 0.0f : __expf(sc[t][2] * scale);
            float e3 = (b1 & 2u) ? 0.0f : __expf(sc[t][3] * scale);
            rs0 += e0 + e1;
            rs1 += e2 + e3;
            int col = n0 + t * 8 + tig * 2;
            u32 w01 = hpair(e0, e1);
            u32 w23 = hpair(e2, e3);
            *(u32*)&er0[col] = w01;
            *(u32*)&er1[col] = w23;
            pa[t >> 1][(t & 1) * 2]     = w01;
            pa[t >> 1][(t & 1) * 2 + 1] = w23;
        }

#pragma unroll
        for (int kk = 0; kk < 8; kk++) {
#pragma unroll
            for (int hh = 0; hh < 4; hh++) {
                u32 bv[4];
                ldsm4t(bv, vs_base + (u32)((kk * 16 + bt_k) * PAW + ((hh * 16 + bt_n) >> 1)) * 4u);
                mma16816(o[2 * hh], pa[kk], &bv[0]);
                mma16816(o[2 * hh + 1], pa[kk], &bv[2]);
            }
        }
        buf ^= 1;
    }

    rs0 += __shfl_xor_sync(0xffffffffu, rs0, 1);
    rs0 += __shfl_xor_sync(0xffffffffu, rs0, 2);
    rs1 += __shfl_xor_sync(0xffffffffu, rs1, 1);
    rs1 += __shfl_xor_sync(0xffffffffu, rs1, 2);
    float iv0 = 1.0f / rs0;
    float iv1 = 1.0f / rs1;
    if (tig == 0) {
        g_inv[(size_t)bh * Sq + m0 + wm + g] = iv0;
        g_inv[(size_t)bh * Sq + m0 + wm + g + 8] = iv1;
    }

    int row = m0 + wm + g;
    int row2 = row + 8;
#pragma unroll
    for (int t = 0; t < 8; t++) {
        int col = t * 8 + tig * 2;
        *(u32*)&g_rep16[(size_t)(b * Sq + row) * Dm + h * DP + col] =
            hpair(o[t][0] * iv0, o[t][1] * iv0);
        *(u32*)&g_rep16[(size_t)(b * Sq + row2) * Dm + h * DP + col] =
            hpair(o[t][2] * iv1, o[t][3] * iv1);
    }
}

// ---------------------------------------------------------------------------
// Normalize: attn[row][col] = e16[row][col] * inv[row]. Pure streaming.
// One block per row; thread t handles 8 halves. (R11-proven, ~8.2 TB/s.)
// ---------------------------------------------------------------------------
__global__ __launch_bounds__(256) void norm_e_kernel(float* __restrict__ attn)
{
    size_t row = blockIdx.x;
    const __half* er = g_e16 + row * Sq;
    float* ar = attn + row * Sq;
    float iv = g_inv[row];
    int t = threadIdx.x;
    uint4 w = *(const uint4*)&er[t * 8];
    const __half2* hp = (const __half2*)&w;
    float2 p0 = __half22float2(hp[0]);
    float2 p1 = __half22float2(hp[1]);
    float2 p2 = __half22float2(hp[2]);
    float2 p3 = __half22float2(hp[3]);
    float4 o0 = make_float4(p0.x * iv, p0.y * iv, p1.x * iv, p1.y * iv);
    float4 o1 = make_float4(p2.x * iv, p2.y * iv, p3.x * iv, p3.y * iv);
    *(float4*)&ar[t * 8] = o0;
    *(float4*)&ar[t * 8 + 4] = o1;
}

// ---------------------------------------------------------------------------
extern "C" void kernel_launch(void* const* d_in, const int* in_sizes, int n_in,
                              void* d_out, int out_size)
{
    const float* Q    = (const float*)d_in[0];
    const float* K    = (const float*)d_in[1];
    const float* V    = (const float*)d_in[2];
    const float* Mask = (const float*)d_in[3];
    const float* Wq   = (const float*)d_in[4];
    const float* bq   = (const float*)d_in[5];
    const float* Wk   = (const float*)d_in[6];
    const float* bk   = (const float*)d_in[7];
    const float* Wv   = (const float*)d_in[8];
    const float* bv   = (const float*)d_in[9];
    const float* Wo   = (const float*)d_in[10];
    const float* bo   = (const float*)d_in[11];

    float* out = (float*)d_out;

    float* attn;
    const size_t attn_elems = (size_t)NBH * Sq * Sq;
    if ((size_t)out_size >= (size_t)OUT_ELEMS + attn_elems) {
        attn = out + OUT_ELEMS;
    } else {
        void* p = nullptr;
        cudaGetSymbolAddress(&p, g_attn_fallback);
        attn = (float*)p;
    }

    static __half *xq, *xk, *xv, *wq, *wk, *wv, *wo, *rep;
    static bool init_done = false;
    if (!init_done) {
        cudaFuncSetAttribute(flash_mma, cudaFuncAttributeMaxDynamicSharedMemorySize, SM_TOT);
        cudaFuncSetAttribute(proj_mma, cudaFuncAttributeMaxDynamicSharedMemorySize, PJ_TOT);
        void* p;
        cudaGetSymbolAddress(&p, g_xq); xq = (__half*)p;
        cudaGetSymbolAddress(&p, g_xk); xk = (__half*)p;
        cudaGetSymbolAddress(&p, g_xv); xv = (__half*)p;
        cudaGetSymbolAddress(&p, g_wq); wq = (__half*)p;
        cudaGetSymbolAddress(&p, g_wk); wk = (__half*)p;
        cudaGetSymbolAddress(&p, g_wv); wv = (__half*)p;
        cudaGetSymbolAddress(&p, g_wo); wo = (__half*)p;
        cudaGetSymbolAddress(&p, g_rep16); rep = (__half*)p;
        init_done = true;
    }

    // converts (merged launches)
    cvt3_kernel<<<dim3(1024, 3), 256>>>(Q, K, V, xq, xk, xv, OUT_ELEMS / 8);
    cvtw_kernel<<<dim3(256, 4), 256>>>(Wq, Wk, Wv, Wo, wq, wk, wv, wo, (Dm * Dm) / 8);

    mask_bits_kernel<<<(Bq * Sq * NMW) / 64, 256>>>(Mask);

    dim3 gProj(MTOK / 128, Dm / 128);            // 64 x 8
    proj_mma<<<gProj, 256, PJ_TOT>>>(xq, wq, bq, nullptr, 0);
    proj_mma<<<gProj, 256, PJ_TOT>>>(xk, wk, bk, nullptr, 1);
    proj_mma<<<gProj, 256, PJ_TOT>>>(xv, wv, bv, nullptr, 2);

    dim3 gAttn(Sq / 128, NBH);                   // 16 x 64
    flash_mma<<<gAttn, 256, SM_TOT>>>();

    norm_e_kernel<<<NBH * Sq, 256>>>(attn);      // 131072 blocks

    proj_mma<<<gProj, 256, PJ_TOT>>>(rep, wo, bo, out, 3);
}

// round 17
// speedup vs baseline: 1.4367x; 1.0700x over previous
#include <cuda_runtime.h>
#include <cuda_fp16.h>
#include <cstdint>
#include <cstddef>

typedef unsigned int u32;

#define Bq 4
#define Sq 2048
#define Dm 1024
#define Hh 16
#define DP 64
#define MTOK (Bq*Sq)          /* 8192 */
#define NBH  (Bq*Hh)          /* 64   */
#define OUT_ELEMS (MTOK*Dm)   /* 8388608 */
#define NMW (Sq/32)           /* 64 mask words per row */

// Scratch (allocation-free rule: __device__ globals)
__device__ __half g_q16[(size_t)NBH*Sq*DP];
__device__ __half g_k16[(size_t)NBH*Sq*DP];
__device__ __half g_v16[(size_t)NBH*Sq*DP];
__device__ __half g_rep16[(size_t)MTOK*Dm];
__device__ __half g_e16[(size_t)NBH*Sq*Sq];      // unnormalized exp scores
__device__ float  g_inv[(size_t)NBH*Sq];          // 1 / rowsum
__device__ u32    g_mbits[(size_t)Bq*Sq*NMW];
__device__ float  g_attn_fallback[(size_t)NBH*Sq*Sq];

// fp16 copies of inputs & weights
__device__ __half g_xq[(size_t)MTOK*Dm];
__device__ __half g_xk[(size_t)MTOK*Dm];
__device__ __half g_xv[(size_t)MTOK*Dm];
__device__ __half g_wq[(size_t)Dm*Dm];
__device__ __half g_wk[(size_t)Dm*Dm];
__device__ __half g_wv[(size_t)Dm*Dm];
__device__ __half g_wo[(size_t)Dm*Dm];

// ---------------------------------------------------------------------------
// helpers
// ---------------------------------------------------------------------------
__device__ __forceinline__ u32 saddr(const void* p) {
    return (u32)__cvta_generic_to_shared(p);
}
__device__ __forceinline__ u32 hpair(float a, float b) {
    __half2 t = __floats2half2_rn(a, b);
    return *reinterpret_cast<u32*>(&t);
}
__device__ __forceinline__ void mma16816(float* c, const u32* a, const u32* b) {
    asm volatile(
        "mma.sync.aligned.m16n8k16.row.col.f32.f16.f16.f32 "
        "{%0,%1,%2,%3},{%4,%5,%6,%7},{%8,%9},{%0,%1,%2,%3};"
        : "+f"(c[0]), "+f"(c[1]), "+f"(c[2]), "+f"(c[3])
        : "r"(a[0]), "r"(a[1]), "r"(a[2]), "r"(a[3]), "r"(b[0]), "r"(b[1]));
}
__device__ __forceinline__ void ldsm4(u32* r, u32 a) {
    asm volatile("ldmatrix.sync.aligned.m8n8.x4.shared.b16 {%0,%1,%2,%3},[%4];"
                 : "=r"(r[0]), "=r"(r[1]), "=r"(r[2]), "=r"(r[3]) : "r"(a));
}
__device__ __forceinline__ void ldsm4t(u32* r, u32 a) {
    asm volatile("ldmatrix.sync.aligned.m8n8.x4.trans.shared.b16 {%0,%1,%2,%3},[%4];"
                 : "=r"(r[0]), "=r"(r[1]), "=r"(r[2]), "=r"(r[3]) : "r"(a));
}
__device__ __forceinline__ void cpa16(u32 dst, const void* src) {
    asm volatile("cp.async.ca.shared.global [%0],[%1],16;\n" :: "r"(dst), "l"(src));
}
__device__ __forceinline__ void cpa_commit() {
    asm volatile("cp.async.commit_group;\n");
}
__device__ __forceinline__ void cpa_wait0() {
    asm volatile("cp.async.wait_group 0;\n");
}

#define PAW 36   /* 64-fp16 row: 32 words + 4 pad (144B pitch) */
#define PBW 68   /* 128-fp16 row: 64 words + 4 pad (272B pitch) */

// ---------------------------------------------------------------------------
// fp32 -> fp16 converts: QKV (3 tensors) in one launch; weights (4) in one.
// ---------------------------------------------------------------------------
__global__ __launch_bounds__(256) void cvt3_kernel(
    const float* __restrict__ A, const float* __restrict__ B,
    const float* __restrict__ C, __half* __restrict__ oa,
    __half* __restrict__ ob, __half* __restrict__ oc, int n8)
{
    const float* in = (blockIdx.y == 0) ? A : (blockIdx.y == 1) ? B : C;
    __half* out = (blockIdx.y == 0) ? oa : (blockIdx.y == 1) ? ob : oc;
    int i = blockIdx.x * 256 + threadIdx.x;
    int stride = gridDim.x * 256;
    for (; i < n8; i += stride) {
        float4 a = *(const float4*)&in[(size_t)i * 8];
        float4 b = *(const float4*)&in[(size_t)i * 8 + 4];
        uint4 w;
        w.x = hpair(a.x, a.y); w.y = hpair(a.z, a.w);
        w.z = hpair(b.x, b.y); w.w = hpair(b.z, b.w);
        *(uint4*)&out[(size_t)i * 8] = w;
    }
}

__global__ __launch_bounds__(256) void cvtw_kernel(
    const float* __restrict__ A, const float* __restrict__ B,
    const float* __restrict__ C, const float* __restrict__ D,
    __half* __restrict__ oa, __half* __restrict__ ob,
    __half* __restrict__ oc, __half* __restrict__ od, int n8)
{
    const float* in = (blockIdx.y == 0) ? A : (blockIdx.y == 1) ? B
                     : (blockIdx.y == 2) ? C : D;
    __half* out = (blockIdx.y == 0) ? oa : (blockIdx.y == 1) ? ob
                 : (blockIdx.y == 2) ? oc : od;
    int i = blockIdx.x * 256 + threadIdx.x;
    int stride = gridDim.x * 256;
    for (; i < n8; i += stride) {
        float4 a = *(const float4*)&in[(size_t)i * 8];
        float4 b = *(const float4*)&in[(size_t)i * 8 + 4];
        uint4 w;
        w.x = hpair(a.x, a.y); w.y = hpair(a.z, a.w);
        w.z = hpair(b.x, b.y); w.w = hpair(b.z, b.w);
        *(uint4*)&out[(size_t)i * 8] = w;
    }
}

// ---------------------------------------------------------------------------
// Mask -> bitmask. 1 bit per mask element (1 = masked). Warp ballot pack.
// ---------------------------------------------------------------------------
__global__ __launch_bounds__(256) void mask_bits_kernel(const float* __restrict__ M)
{
    int wgl = blockIdx.x * 8 + (threadIdx.x >> 5);
    int lane = threadIdx.x & 31;
#pragma unroll
    for (int i = 0; i < 8; i++) {
        size_t word = (size_t)wgl * 8 + i;
        float v = M[word * 32 + lane];
        u32 bal = __ballot_sync(0xffffffffu, v != 0.0f);
        if (lane == 0) { g_mbits[word] = bal; }
    }
}

// ---------------------------------------------------------------------------
// Projection GEMM, pure fp16 + cp.async double buffer.
// mode 0: merged QKV — blockIdx.z selects (X,W,bias,target=z).
// mode 1: out projection — X0/W0/b0, fp32 row-major to dout.
// ---------------------------------------------------------------------------
#define PJ_XS0 0
#define PJ_XS1 18432
#define PJ_WS0 36864
#define PJ_WS1 54272
#define PJ_TOT 71680

__global__ __launch_bounds__(256) void proj_mma(
    const __half* __restrict__ X0, const __half* __restrict__ X1,
    const __half* __restrict__ X2,
    const __half* __restrict__ W0, const __half* __restrict__ W1,
    const __half* __restrict__ W2,
    const float* __restrict__ b0p, const float* __restrict__ b1p,
    const float* __restrict__ b2p,
    float* __restrict__ dout, int mode)
{
    extern __shared__ __align__(16) char sm[];

    const int tid = threadIdx.x;
    const int m0 = blockIdx.x * 128, n0 = blockIdx.y * 128;
    const int z = blockIdx.z;
    const int target = (mode == 1) ? 3 : z;
    const __half* X16 = (z == 0) ? X0 : (z == 1) ? X1 : X2;
    const __half* W16 = (z == 0) ? W0 : (z == 1) ? W1 : W2;
    const float* bias = (z == 0) ? b0p : (z == 1) ? b1p : b2p;

    const int warp = tid >> 5, lane = tid & 31;
    const int wm = (warp >> 2) * 64, wn = (warp & 3) * 32;
    const int g = lane >> 2, tig = lane & 3;

    const int a_row = (lane & 7) + ((lane >> 3) & 1) * 8;
    const int a_k   = (lane >> 4) * 8;
    const int bt_k  = (lane & 7) + ((lane >> 3) & 1) * 8;
    const int bt_n  = (lane >> 4) * 8;

    const u32 smb = saddr(sm);

    float acc[4][4][4];
#pragma unroll
    for (int i = 0; i < 4; i++) {
#pragma unroll
        for (int j = 0; j < 4; j++) {
#pragma unroll
            for (int r = 0; r < 4; r++) { acc[i][j][r] = 0.0f; }
        }
    }

    {
        u32 xd = smb + PJ_XS0, wd = smb + PJ_WS0;
#pragma unroll
        for (int l = 0; l < 4; l++) {
            int idx = tid + l * 256;
            int r = idx >> 3, c = idx & 7;
            cpa16(xd + (u32)(r * PAW + c * 4) * 4u, X16 + (size_t)(m0 + r) * Dm + c * 8);
        }
#pragma unroll
        for (int l = 0; l < 4; l++) {
            int idx = tid + l * 256;
            int r = idx >> 4, c = idx & 15;
            cpa16(wd + (u32)(r * PBW + c * 4) * 4u, W16 + (size_t)r * Dm + n0 + c * 8);
        }
        cpa_commit();
    }

    int buf = 0;
    for (int it = 0; it < 16; it++) {
        cpa_wait0();
        __syncthreads();

        if (it < 15) {
            int kk0 = (it + 1) * 64;
            int nb = buf ^ 1;
            u32 xd = smb + (nb ? PJ_XS1 : PJ_XS0);
            u32 wd = smb + (nb ? PJ_WS1 : PJ_WS0);
#pragma unroll
            for (int l = 0; l < 4; l++) {
                int idx = tid + l * 256;
                int r = idx >> 3, c = idx & 7;
                cpa16(xd + (u32)(r * PAW + c * 4) * 4u, X16 + (size_t)(m0 + r) * Dm + kk0 + c * 8);
            }
#pragma unroll
            for (int l = 0; l < 4; l++) {
                int idx = tid + l * 256;
                int r = idx >> 4, c = idx & 15;
                cpa16(wd + (u32)(r * PBW + c * 4) * 4u, W16 + (size_t)(kk0 + r) * Dm + n0 + c * 8);
            }
            cpa_commit();
        }

        const u32 as_base = smb + (buf ? PJ_XS1 : PJ_XS0);
        const u32 bs_base = smb + (buf ? PJ_WS1 : PJ_WS0);

#pragma unroll
        for (int ks = 0; ks < 64; ks += 16) {
            u32 af[4][4];
#pragma unroll
            for (int mi = 0; mi < 4; mi++) {
                ldsm4(af[mi], as_base + (u32)((wm + mi * 16 + a_row) * PAW + ((ks + a_k) >> 1)) * 4u);
            }
            u32 bf[2][4];
#pragma unroll
            for (int h = 0; h < 2; h++) {
                ldsm4t(bf[h], bs_base + (u32)((ks + bt_k) * PBW + ((wn + h * 16 + bt_n) >> 1)) * 4u);
            }
#pragma unroll
            for (int mi = 0; mi < 4; mi++) {
#pragma unroll
                for (int j = 0; j < 4; j++) {
                    mma16816(acc[mi][j], af[mi], &bf[j >> 1][(j & 1) * 2]);
                }
            }
        }
        __syncthreads();
        buf ^= 1;
    }

    __half* hs_out = (target == 0) ? g_q16 : (target == 1) ? g_k16 : g_v16;
#pragma unroll
    for (int mi = 0; mi < 4; mi++) {
        int row = m0 + wm + mi * 16 + g;
        int row2 = row + 8;
#pragma unroll
        for (int j = 0; j < 4; j++) {
            int col = n0 + wn + j * 8 + tig * 2;
            float b0 = bias[col], b1 = bias[col + 1];
            float c00 = acc[mi][j][0] + b0, c01 = acc[mi][j][1] + b1;
            float c10 = acc[mi][j][2] + b0, c11 = acc[mi][j][3] + b1;
            if (target < 3) {
                int h = col >> 6, dc = col & 63;
                int bi = row >> 11, sl = row & 2047;
                int bi2 = row2 >> 11, sl2 = row2 & 2047;
                *(u32*)&hs_out[((size_t)(bi * Hh + h) * Sq + sl) * DP + dc] = hpair(c00, c01);
                *(u32*)&hs_out[((size_t)(bi2 * Hh + h) * Sq + sl2) * DP + dc] = hpair(c10, c11);
            } else {
                *(float2*)&dout[(size_t)row * Dm + col] = make_float2(c00, c01);
                *(float2*)&dout[(size_t)row2 * Dm + col] = make_float2(c10, c11);
            }
        }
    }
}

// ---------------------------------------------------------------------------
// Fused flash attention pass, half-tile pipelined (reduces register pressure):
// per 128-col K/V tile, process two 64-col halves: QK(half) -> exp/store/
// repack(half) -> PV(half). sc shrinks 64->32 regs; peak live < 128.
// ---------------------------------------------------------------------------
#define SM_QS   0
#define SM_KS   18432
#define SM_VS   55296
#define SM_MS   92160
#define SM_TOT  96256

__global__ __launch_bounds__(256) void flash_mma()
{
    extern __shared__ __align__(16) char sm[];
    const int tid = threadIdx.x;
    const int bh = blockIdx.y, b = bh >> 4, h = bh & 15;
    const int m0 = blockIdx.x * 128;
    const __half* Qp = g_q16 + (size_t)bh * Sq * DP;
    const __half* Kp = g_k16 + (size_t)bh * Sq * DP;
    const __half* Vp = g_v16 + (size_t)bh * Sq * DP;
    const int warp = tid >> 5, lane = tid & 31;
    const int wm = warp * 16;
    const int g = lane >> 2, tig = lane & 3;

    const int a_row = (lane & 7) + ((lane >> 3) & 1) * 8;
    const int a_k   = (lane >> 4) * 8;
    const int bn_n  = (lane & 7) + (lane >> 4) * 8;
    const int bn_k  = ((lane >> 3) & 1) * 8;
    const int bt_k  = (lane & 7) + ((lane >> 3) & 1) * 8;
    const int bt_n  = (lane >> 4) * 8;

    const u32 smb = saddr(sm);
    u32* Qs = (u32*)(sm + SM_QS);

#pragma unroll
    for (int l = 0; l < 4; l++) {
        int idx = tid + l * 256;
        int r = idx >> 3, q = idx & 7;
        *(uint4*)&Qs[r * PAW + q * 4] = *(const uint4*)&Qp[(size_t)(m0 + r) * DP + q * 8];
    }

    {
        u32 ksb = smb + SM_KS, vsb = smb + SM_VS, msb = smb + SM_MS;
#pragma unroll
        for (int l = 0; l < 4; l++) {
            int idx = tid + l * 256;
            int r = idx >> 3, c = idx & 7;
            cpa16(ksb + (u32)(r * PAW + c * 4) * 4u, Kp + (size_t)r * DP + c * 8);
            cpa16(vsb + (u32)(r * PAW + c * 4) * 4u, Vp + (size_t)r * DP + c * 8);
        }
        if (tid < 128) {
            cpa16(msb + tid * 16, g_mbits + (size_t)(b * Sq + m0 + tid) * NMW);
        }
        cpa_commit();
    }
    __syncthreads();

    u32 af[4][4];
#pragma unroll
    for (int ks = 0; ks < 4; ks++) {
        ldsm4(af[ks], smb + SM_QS + (u32)((wm + a_row) * PAW + ((ks * 16 + a_k) >> 1)) * 4u);
    }

    float o[8][4];
#pragma unroll
    for (int t = 0; t < 8; t++) {
#pragma unroll
        for (int r = 0; r < 4; r++) { o[t][r] = 0.0f; }
    }
    float rs0 = 0.0f, rs1 = 0.0f;

    const float scale = 0.125f;
    __half* er0 = g_e16 + ((size_t)bh * Sq + m0 + wm + g) * Sq;
    __half* er1 = g_e16 + ((size_t)bh * Sq + m0 + wm + g + 8) * Sq;

    int buf = 0;
    for (int it = 0; it < 16; it++) {
        int n0 = it * 128;
        cpa_wait0();
        __syncthreads();

        if (it < 15) {
            int nn = n0 + 128;
            int nb = buf ^ 1;
            u32 ksb = smb + SM_KS + nb * 18432;
            u32 vsb = smb + SM_VS + nb * 18432;
            u32 msb = smb + SM_MS + nb * 2048;
#pragma unroll
            for (int l = 0; l < 4; l++) {
                int idx = tid + l * 256;
                int r = idx >> 3, c = idx & 7;
                cpa16(ksb + (u32)(r * PAW + c * 4) * 4u, Kp + (size_t)(nn + r) * DP + c * 8);
                cpa16(vsb + (u32)(r * PAW + c * 4) * 4u, Vp + (size_t)(nn + r) * DP + c * 8);
            }
            if (tid < 128) {
                cpa16(msb + tid * 16, g_mbits + (size_t)(b * Sq + m0 + tid) * NMW + (nn >> 5));
            }
            cpa_commit();
        }

        const u32 ks_base = smb + SM_KS + buf * 18432;
        const u32 vs_base = smb + SM_VS + buf * 18432;
        const uint4* Ms = (const uint4*)(sm + SM_MS + buf * 2048);

        uint4 mq0 = Ms[wm + g];
        uint4 mq1 = Ms[wm + g + 8];
        const u32* mw0 = (const u32*)&mq0;
        const u32* mw1 = (const u32*)&mq1;

#pragma unroll
        for (int half = 0; half < 2; half++) {
            const int hb = half * 64;

            float sc[8][4];
#pragma unroll
            for (int t = 0; t < 8; t++) {
#pragma unroll
                for (int r = 0; r < 4; r++) { sc[t][r] = 0.0f; }
            }
#pragma unroll
            for (int ks = 0; ks < 4; ks++) {
#pragma unroll
                for (int h6 = 0; h6 < 4; h6++) {
                    u32 bq[4];
                    ldsm4(bq, ks_base + (u32)((hb + h6 * 16 + bn_n) * PAW + ((ks * 16 + bn_k) >> 1)) * 4u);
                    mma16816(sc[2 * h6], af[ks], &bq[0]);
                    mma16816(sc[2 * h6 + 1], af[ks], &bq[2]);
                }
            }

            u32 pa[4][4];
#pragma unroll
            for (int t = 0; t < 8; t++) {
                int bp = hb + t * 8 + tig * 2;
                u32 b0 = (mw0[bp >> 5] >> (bp & 31)) & 3u;
                u32 b1 = (mw1[bp >> 5] >> (bp & 31)) & 3u;
                float e0 = (b0 & 1u) ? 0.0f : __expf(sc[t][0] * scale);
                float e1 = (b0 & 2u) ? 0.0f : __expf(sc[t][1] * scale);
                float e2 = (b1 & 1u) ? 0.0f : __expf(sc[t][2] * scale);
                float e3 = (b1 & 2u) ? 0.0f : __expf(sc[t][3] * scale);
                rs0 += e0 + e1;
                rs1 += e2 + e3;
                int col = n0 + bp;
                u32 w01 = hpair(e0, e1);
                u32 w23 = hpair(e2, e3);
                *(u32*)&er0[col] = w01;
                *(u32*)&er1[col] = w23;
                pa[t >> 1][(t & 1) * 2]     = w01;
                pa[t >> 1][(t & 1) * 2 + 1] = w23;
            }

#pragma unroll
            for (int kk = 0; kk < 4; kk++) {
#pragma unroll
                for (int hh = 0; hh < 4; hh++) {
                    u32 bv[4];
                    ldsm4t(bv, vs_base + (u32)((hb + kk * 16 + bt_k) * PAW + ((hh * 16 + bt_n) >> 1)) * 4u);
                    mma16816(o[2 * hh], pa[kk], &bv[0]);
                    mma16816(o[2 * hh + 1], pa[kk], &bv[2]);
                }
            }
        }
        buf ^= 1;
    }

    rs0 += __shfl_xor_sync(0xffffffffu, rs0, 1);
    rs0 += __shfl_xor_sync(0xffffffffu, rs0, 2);
    rs1 += __shfl_xor_sync(0xffffffffu, rs1, 1);
    rs1 += __shfl_xor_sync(0xffffffffu, rs1, 2);
    float iv0 = 1.0f / rs0;
    float iv1 = 1.0f / rs1;
    if (tig == 0) {
        g_inv[(size_t)bh * Sq + m0 + wm + g] = iv0;
        g_inv[(size_t)bh * Sq + m0 + wm + g + 8] = iv1;
    }

    int row = m0 + wm + g;
    int row2 = row + 8;
#pragma unroll
    for (int t = 0; t < 8; t++) {
        int col = t * 8 + tig * 2;
        *(u32*)&g_rep16[(size_t)(b * Sq + row) * Dm + h * DP + col] =
            hpair(o[t][0] * iv0, o[t][1] * iv0);
        *(u32*)&g_rep16[(size_t)(b * Sq + row2) * Dm + h * DP + col] =
            hpair(o[t][2] * iv1, o[t][3] * iv1);
    }
}

// ---------------------------------------------------------------------------
// Normalize: attn[row][col] = e16[row][col] * inv[row]. Pure streaming.
// ---------------------------------------------------------------------------
__global__ __launch_bounds__(256) void norm_e_kernel(float* __restrict__ attn)
{
    size_t row = blockIdx.x;
    const __half* er = g_e16 + row * Sq;
    float* ar = attn + row * Sq;
    float iv = g_inv[row];
    int t = threadIdx.x;
    uint4 w = *(const uint4*)&er[t * 8];
    const __half2* hp = (const __half2*)&w;
    float2 p0 = __half22float2(hp[0]);
    float2 p1 = __half22float2(hp[1]);
    float2 p2 = __half22float2(hp[2]);
    float2 p3 = __half22float2(hp[3]);
    float4 o0 = make_float4(p0.x * iv, p0.y * iv, p1.x * iv, p1.y * iv);
    float4 o1 = make_float4(p2.x * iv, p2.y * iv, p3.x * iv, p3.y * iv);
    *(float4*)&ar[t * 8] = o0;
    *(float4*)&ar[t * 8 + 4] = o1;
}

// ---------------------------------------------------------------------------
extern "C" void kernel_launch(void* const* d_in, const int* in_sizes, int n_in,
                              void* d_out, int out_size)
{
    const float* Q    = (const float*)d_in[0];
    const float* K    = (const float*)d_in[1];
    const float* V    = (const float*)d_in[2];
    const float* Mask = (const float*)d_in[3];
    const float* Wq   = (const float*)d_in[4];
    const float* bq   = (const float*)d_in[5];
    const float* Wk   = (const float*)d_in[6];
    const float* bk   = (const float*)d_in[7];
    const float* Wv   = (const float*)d_in[8];
    const float* bv   = (const float*)d_in[9];
    const float* Wo   = (const float*)d_in[10];
    const float* bo   = (const float*)d_in[11];

    float* out = (float*)d_out;

    float* attn;
    const size_t attn_elems = (size_t)NBH * Sq * Sq;
    if ((size_t)out_size >= (size_t)OUT_ELEMS + attn_elems) {
        attn = out + OUT_ELEMS;
    } else {
        void* p = nullptr;
        cudaGetSymbolAddress(&p, g_attn_fallback);
        attn = (float*)p;
    }

    static __half *xq, *xk, *xv, *wq, *wk, *wv, *wo, *rep;
    static bool init_done = false;
    if (!init_done) {
        cudaFuncSetAttribute(flash_mma, cudaFuncAttributeMaxDynamicSharedMemorySize, SM_TOT);
        cudaFuncSetAttribute(proj_mma, cudaFuncAttributeMaxDynamicSharedMemorySize, PJ_TOT);
        void* p;
        cudaGetSymbolAddress(&p, g_xq); xq = (__half*)p;
        cudaGetSymbolAddress(&p, g_xk); xk = (__half*)p;
        cudaGetSymbolAddress(&p, g_xv); xv = (__half*)p;
        cudaGetSymbolAddress(&p, g_wq); wq = (__half*)p;
        cudaGetSymbolAddress(&p, g_wk); wk = (__half*)p;
        cudaGetSymbolAddress(&p, g_wv); wv = (__half*)p;
        cudaGetSymbolAddress(&p, g_wo); wo = (__half*)p;
        cudaGetSymbolAddress(&p, g_rep16); rep = (__half*)p;
        init_done = true;
    }

    // converts (merged launches)
    cvt3_kernel<<<dim3(1024, 3), 256>>>(Q, K, V, xq, xk, xv, OUT_ELEMS / 8);
    cvtw_kernel<<<dim3(256, 4), 256>>>(Wq, Wk, Wv, Wo, wq, wk, wv, wo, (Dm * Dm) / 8);

    mask_bits_kernel<<<(Bq * Sq * NMW) / 64, 256>>>(Mask);

    // merged QKV projection: grid.z = 3
    dim3 gProjQKV(MTOK / 128, Dm / 128, 3);      // 64 x 8 x 3
    proj_mma<<<gProjQKV, 256, PJ_TOT>>>(xq, xk, xv, wq, wk, wv, bq, bk, bv,
                                        nullptr, 0);

    dim3 gAttn(Sq / 128, NBH);                   // 16 x 64
    flash_mma<<<gAttn, 256, SM_TOT>>>();

    norm_e_kernel<<<NBH * Sq, 256>>>(attn);      // 131072 blocks

    dim3 gProjO(MTOK / 128, Dm / 128, 1);        // 64 x 8
    proj_mma<<<gProjO, 256, PJ_TOT>>>(rep, rep, rep, wo, wo, wo, bo, bo, bo,
                                      out, 1);
}